// round 8
// baseline (speedup 1.0000x reference)
#include <cuda_runtime.h>

// Fixed shapes: preds/targets [32, 2048, 512] f32, lengths [32] i32 (sorted desc).
#define BB 32
#define TT 2048
#define DD 512
#define PAIRS 16    // pair p = (b1=p, b2=31-p): near-constant total work per pair
#define TPP 128     // blocks (tiles) per pair; grid = 16*128 = 2048

// Scratch (device globals; every slot rewritten each launch; counters wrap
// back to 0 -> graph-replay-safe, no init kernel).
__device__ float    g_S[PAIRS * TPP * 2 * DD];  // per-(pair,tile,{b1,b2},d) partials, 8 MiB
__device__ float    g_wordP[PAIRS * TPP];       // per-block word-loss partials
__device__ float    g_sentB[BB];                // per-b sentence term
__device__ unsigned g_ctrP[PAIRS];              // per-pair arrival counters (wrap at TPP-1)
__device__ unsigned g_ctr;                      // global arrival counter (wrap at PAIRS-1)

__device__ __forceinline__ float sl1(float d) {
    float ad = fabsf(d);
    return ad < 1.0f ? 0.5f * d * d : ad - 0.5f;
}

// Accumulate one row (float4 at column dg) into sd/w.
__device__ __forceinline__ void acc_row(const float* __restrict__ p,
                                        const float* __restrict__ q,
                                        float4& sd, float& w) {
    const float4 pv = __ldcs(reinterpret_cast<const float4*>(p));
    const float4 qv = __ldcs(reinterpret_cast<const float4*>(q));
    float dx = pv.x - qv.x, dy = pv.y - qv.y, dz = pv.z - qv.z, dw = pv.w - qv.w;
    sd.x += dx; sd.y += dy; sd.z += dz; sd.w += dw;
    w += sl1(dx) + sl1(dy) + sl1(dz) + sl1(dw);
}

// grid = (TPP, PAIRS), block = 256 (2 row-streams x 128 float4 lanes).
__global__ __launch_bounds__(256)
void k_fused(const float* __restrict__ preds,
             const float* __restrict__ targs,
             const int* __restrict__ lens,
             float* __restrict__ out) {
    const int pair = blockIdx.y;
    const int tile = blockIdx.x;
    const int tid  = threadIdx.x;
    const int sub  = tid >> 7;            // 0/1
    const int lane = tid & 127;
    const int dg   = lane << 2;           // float4 column group (covers D=512)

    const int b1 = pair, b2 = BB - 1 - pair;
    const int len1 = lens[b1], len2 = lens[b2];
    const int L = len1 + len2;            // pair row-space

    const float* p1 = preds + (size_t)b1 * TT * DD + dg;
    const float* q1 = targs + (size_t)b1 * TT * DD + dg;
    const float* p2 = preds + (size_t)b2 * TT * DD + dg;
    const float* q2 = targs + (size_t)b2 * TT * DD + dg;

    // ---- Phase 1: stream this block's strided rows of the pair row-space ----
    float4 sdA = make_float4(0.f, 0.f, 0.f, 0.f);   // b1 diff-sum
    float4 sdB = make_float4(0.f, 0.f, 0.f, 0.f);   // b2 diff-sum
    float  w = 0.f;
    const int STEP = 2 * TPP;             // 256 rows between this thread's rows

    int r = tile + sub * TPP;
    // b1 rows (unroll x2: 4 LDG.128 in flight)
    for (; r + STEP < len1; r += 2 * STEP) {
        acc_row(p1 + (size_t)r * DD,          q1 + (size_t)r * DD,          sdA, w);
        acc_row(p1 + (size_t)(r + STEP) * DD, q1 + (size_t)(r + STEP) * DD, sdA, w);
    }
    if (r < len1) { acc_row(p1 + (size_t)r * DD, q1 + (size_t)r * DD, sdA, w); r += STEP; }
    // b2 rows
    for (; r + STEP < L; r += 2 * STEP) {
        const int t0 = r - len1, t1 = r + STEP - len1;
        acc_row(p2 + (size_t)t0 * DD, q2 + (size_t)t0 * DD, sdB, w);
        acc_row(p2 + (size_t)t1 * DD, q2 + (size_t)t1 * DD, sdB, w);
    }
    if (r < L) { const int t0 = r - len1; acc_row(p2 + (size_t)t0 * DD, q2 + (size_t)t0 * DD, sdB, w); }

    // Combine sub0+sub1 via shared; two slots per block (b1, b2).
    __shared__ float4 shA[128], shB[128];
    __shared__ float  sw[256];
    __shared__ bool   is_last_p, is_last_g;
    if (sub == 1) { shA[lane] = sdA; shB[lane] = sdB; }
    sw[tid] = w;
    __syncthreads();
    if (sub == 0) {
        float4 oa = shA[lane], ob = shB[lane];
        sdA.x += oa.x; sdA.y += oa.y; sdA.z += oa.z; sdA.w += oa.w;
        sdB.x += ob.x; sdB.y += ob.y; sdB.z += ob.z; sdB.w += ob.w;
        float* slot = g_S + ((size_t)(pair * TPP + tile) * 2) * DD + dg;
        *reinterpret_cast<float4*>(slot)      = sdA;
        *reinterpret_cast<float4*>(slot + DD) = sdB;
    }

    // Block-reduce the word partial.
    #pragma unroll
    for (int s = 128; s > 0; s >>= 1) {
        if (tid < s) sw[tid] += sw[tid + s];
        __syncthreads();
    }
    if (tid == 0) {
        g_wordP[pair * TPP + tile] = sw[0];
        __threadfence();
        unsigned prev = atomicInc(&g_ctrP[pair], TPP - 1u);  // wraps -> replay-safe
        is_last_p = (prev == TPP - 1u);
    }
    __syncthreads();
    if (!is_last_p) return;

    // ---- Phase 2 (last block of pair): fold TPP slots for b1 and b2, L2-hot ----
    __threadfence();   // acquire: see all TPP blocks' g_S writes for this pair

    #pragma unroll
    for (int which = 0; which < 2; which++) {
        float4 s4 = make_float4(0.f, 0.f, 0.f, 0.f);
        const float* Sp = g_S + ((size_t)(pair * TPP) * 2 + which) * DD + dg;
        for (int j = sub * (TPP / 2); j < (sub + 1) * (TPP / 2); j++) {
            const float4 v = *reinterpret_cast<const float4*>(Sp + (size_t)j * 2 * DD);
            s4.x += v.x; s4.y += v.y; s4.z += v.z; s4.w += v.w;
        }
        __syncthreads();
        if (sub == 1) shA[lane] = s4;
        __syncthreads();
        float wsent = 0.f;
        if (sub == 0) {
            const float4 o = shA[lane];
            s4.x += o.x; s4.y += o.y; s4.z += o.z; s4.w += o.w;
            const float invlen = 1.0f / (float)(which == 0 ? len1 : len2);
            wsent = sl1(s4.x * invlen) + sl1(s4.y * invlen)
                  + sl1(s4.z * invlen) + sl1(s4.w * invlen);
        }
        sw[tid] = wsent;
        __syncthreads();
        #pragma unroll
        for (int s = 128; s > 0; s >>= 1) {
            if (tid < s) sw[tid] += sw[tid + s];
            __syncthreads();
        }
        if (tid == 0) g_sentB[which == 0 ? b1 : b2] = sw[0] * (1.0f / (float)DD);
        __syncthreads();
    }
    if (tid == 0) {
        __threadfence();
        unsigned prev = atomicInc(&g_ctr, PAIRS - 1u);
        is_last_g = (prev == PAIRS - 1u);
    }
    __syncthreads();
    if (!is_last_g) return;

    // ---- Phase 3 (single final block): scalar combine, L2-hot ----
    __threadfence();

    float wsum = 0.f;
    #pragma unroll
    for (int i = tid; i < PAIRS * TPP; i += 256) wsum += g_wordP[i];
    float ssum = 0.f;
    int   lsum = 0;
    if (tid < BB) { ssum = g_sentB[tid]; lsum = lens[tid]; }

    __shared__ float swd[256];
    __shared__ float ssn[256];
    __shared__ int   sln[256];
    swd[tid] = wsum; ssn[tid] = ssum; sln[tid] = lsum;
    __syncthreads();
    #pragma unroll
    for (int s = 128; s > 0; s >>= 1) {
        if (tid < s) {
            swd[tid] += swd[tid + s];
            ssn[tid] += ssn[tid + s];
            sln[tid] += sln[tid + s];
        }
        __syncthreads();
    }
    if (tid == 0) {
        const float n_valid = (float)sln[0] * (float)DD;   // <= 2^25, exact
        out[0] = swd[0] / n_valid + ssn[0] * (1.0f / (float)BB);
    }
}

extern "C" void kernel_launch(void* const* d_in, const int* in_sizes, int n_in,
                              void* d_out, int out_size) {
    const float* preds = (const float*)d_in[0];
    const float* targs = (const float*)d_in[1];
    const int*   lens  = (const int*)d_in[2];
    float* out = (float*)d_out;

    k_fused<<<dim3(TPP, PAIRS), 256>>>(preds, targs, lens, out);
}

// round 9
// speedup vs baseline: 1.2572x; 1.2572x over previous
#include <cuda_runtime.h>
#include <cuda_pipeline.h>

// Fixed shapes: preds/targets [32, 2048, 512] f32, lengths [32] i32.
#define BB 32
#define TT 2048
#define DD 512
#define TILES 64     // blocks (t-tiles) per batch row, strided t assignment
#define STAGES 4     // smem pipeline ring
#define PRE 3        // groups in flight

// Scratch (device globals; every slot rewritten each launch; counters wrap
// back to 0 -> graph-replay-safe, no init kernel).
__device__ float    g_S[BB * TILES * DD];   // per-(b,tile,d) diff-sum partials, 4 MiB
__device__ float    g_wordP[BB * TILES];    // per-block word-loss partials (2048)
__device__ float    g_sentB[BB];            // per-b sentence term
__device__ unsigned g_ctrB[BB];             // per-b arrival counters (wrap at TILES-1)
__device__ unsigned g_ctr;                  // global arrival counter (wrap at BB-1)

__device__ __forceinline__ float sl1(float d) {
    float ad = fabsf(d);
    return ad < 1.0f ? 0.5f * d * d : ad - 0.5f;
}

// One fused kernel. grid = (TILES, BB), block = 256 (2 t-rows x 128 float4 lanes).
// Streaming loads go gmem -> smem via cp.async (bypasses RF + L1); each thread
// consumes only its own smem slots, so the pipeline needs no block barriers.
__global__ __launch_bounds__(256)
void k_fused(const float* __restrict__ preds,
             const float* __restrict__ targs,
             const int* __restrict__ lens,
             float* __restrict__ out) {
    const int b    = blockIdx.y;
    const int tile = blockIdx.x;
    const int tid  = threadIdx.x;
    const int sub  = tid >> 7;            // 0/1: which row of the pair
    const int lane = tid & 127;
    const int dg   = lane << 2;           // float4 column group (covers D=512)

    const int len = lens[b];

    const float* pbase = preds + (size_t)b * TT * DD + dg;
    const float* qbase = targs + (size_t)b * TT * DD + dg;

    // Pipeline ring: [stage][stream(P/T)][sub][lane] float4 = 32 KB.
    __shared__ float4 buf[STAGES * 2 * 2 * 128];
    #define SLOT(s, st) (&buf[((((s) * 2 + (st)) * 2) + sub) * 128 + lane])

    const int tb = tile + sub * TILES;    // this thread's first row
    const int K  = (len + 127) >> 7;      // stages = ceil(len / 128); >= 1

    // ---- Phase 1: cp.async pipelined stream ----
    float4 sd = make_float4(0.f, 0.f, 0.f, 0.f);
    float  w  = 0.f;

    // prologue: stages 0..PRE-1
    #pragma unroll
    for (int k = 0; k < PRE; k++) {
        const int t = tb + (k << 7);
        if (k < K) {
            if (t < len) {
                __pipeline_memcpy_async(SLOT(k & (STAGES - 1), 0), pbase + (size_t)t * DD, 16);
                __pipeline_memcpy_async(SLOT(k & (STAGES - 1), 1), qbase + (size_t)t * DD, 16);
            } else {
                *SLOT(k & (STAGES - 1), 0) = make_float4(0.f, 0.f, 0.f, 0.f);
                *SLOT(k & (STAGES - 1), 1) = make_float4(0.f, 0.f, 0.f, 0.f);
            }
        }
        __pipeline_commit();
    }

    for (int k = 0; k < K; k++) {
        // issue stage k+PRE (slot (k-1)%STAGES: consumed last iteration)
        {
            const int kk = k + PRE;
            const int t  = tb + (kk << 7);
            if (kk < K) {
                if (t < len) {
                    __pipeline_memcpy_async(SLOT(kk & (STAGES - 1), 0), pbase + (size_t)t * DD, 16);
                    __pipeline_memcpy_async(SLOT(kk & (STAGES - 1), 1), qbase + (size_t)t * DD, 16);
                } else {
                    *SLOT(kk & (STAGES - 1), 0) = make_float4(0.f, 0.f, 0.f, 0.f);
                    *SLOT(kk & (STAGES - 1), 1) = make_float4(0.f, 0.f, 0.f, 0.f);
                }
            }
            __pipeline_commit();
        }
        __pipeline_wait_prior(PRE);       // stage k's group complete
        const float4 pv = *SLOT(k & (STAGES - 1), 0);
        const float4 tv = *SLOT(k & (STAGES - 1), 1);
        float dx = pv.x - tv.x, dy = pv.y - tv.y, dz = pv.z - tv.z, dw = pv.w - tv.w;
        sd.x += dx; sd.y += dy; sd.z += dz; sd.w += dw;
        w += sl1(dx) + sl1(dy) + sl1(dz) + sl1(dw);
    }
    __pipeline_wait_prior(0);
    #undef SLOT

    // Combine sub0+sub1 diff-sums via shared; one slot per (b,tile).
    __shared__ float4 sh4[128];
    __shared__ float  sw[256];
    __shared__ bool   is_last_b, is_last_g;
    if (sub == 1) sh4[lane] = sd;
    sw[tid] = w;
    __syncthreads();
    if (sub == 0) {
        const float4 o = sh4[lane];
        sd.x += o.x; sd.y += o.y; sd.z += o.z; sd.w += o.w;
        *reinterpret_cast<float4*>(g_S + ((size_t)(b * TILES + tile)) * DD + dg) = sd;
    }

    // Block-reduce the word partial.
    #pragma unroll
    for (int s = 128; s > 0; s >>= 1) {
        if (tid < s) sw[tid] += sw[tid + s];
        __syncthreads();
    }
    if (tid == 0) {
        g_wordP[b * TILES + tile] = sw[0];
        __threadfence();
        // wraps to 0 after TILES arrivals -> self-resetting across replays
        unsigned prev = atomicInc(&g_ctrB[b], TILES - 1u);
        is_last_b = (prev == TILES - 1u);
    }
    __syncthreads();
    if (!is_last_b) return;

    // ---- Phase 2 (last block of this b): fold 64 partial slots, L2-hot ----
    __threadfence();  // acquire: see all 64 blocks' g_S writes for this b

    float4 s4 = make_float4(0.f, 0.f, 0.f, 0.f);
    const float* Sb = g_S + (size_t)b * TILES * DD;
    #pragma unroll
    for (int j = sub * (TILES / 2); j < (sub + 1) * (TILES / 2); j++) {
        const float4 v = *reinterpret_cast<const float4*>(Sb + (size_t)j * DD + dg);
        s4.x += v.x; s4.y += v.y; s4.z += v.z; s4.w += v.w;
    }
    __syncthreads();   // sh4 reuse
    if (sub == 1) sh4[lane] = s4;
    __syncthreads();
    float wsent = 0.f;
    if (sub == 0) {
        const float4 o = sh4[lane];
        s4.x += o.x; s4.y += o.y; s4.z += o.z; s4.w += o.w;
        const float invlen = 1.0f / (float)len;
        wsent = sl1(s4.x * invlen) + sl1(s4.y * invlen)
              + sl1(s4.z * invlen) + sl1(s4.w * invlen);
    }
    sw[tid] = wsent;
    __syncthreads();
    #pragma unroll
    for (int s = 128; s > 0; s >>= 1) {
        if (tid < s) sw[tid] += sw[tid + s];
        __syncthreads();
    }
    if (tid == 0) {
        g_sentB[b] = sw[0] * (1.0f / (float)DD);
        __threadfence();
        unsigned prev = atomicInc(&g_ctr, BB - 1u);
        is_last_g = (prev == BB - 1u);
    }
    __syncthreads();
    if (!is_last_g) return;

    // ---- Phase 3 (single final block): scalar combine, L2-hot ----
    __threadfence();

    float wsum = 0.f;
    #pragma unroll
    for (int i = tid; i < BB * TILES; i += 256) wsum += g_wordP[i];
    float ssum = 0.f;
    int   lsum = 0;
    if (tid < BB) { ssum = g_sentB[tid]; lsum = lens[tid]; }

    __shared__ float swd[256];
    __shared__ float ssn[256];
    __shared__ int   sln[256];
    swd[tid] = wsum; ssn[tid] = ssum; sln[tid] = lsum;
    __syncthreads();
    #pragma unroll
    for (int s = 128; s > 0; s >>= 1) {
        if (tid < s) {
            swd[tid] += swd[tid + s];
            ssn[tid] += ssn[tid + s];
            sln[tid] += sln[tid + s];
        }
        __syncthreads();
    }
    if (tid == 0) {
        const float n_valid = (float)sln[0] * (float)DD;  // <= 2^25, exact
        out[0] = swd[0] / n_valid + ssn[0] * (1.0f / (float)BB);
    }
}

extern "C" void kernel_launch(void* const* d_in, const int* in_sizes, int n_in,
                              void* d_out, int out_size) {
    const float* preds = (const float*)d_in[0];
    const float* targs = (const float*)d_in[1];
    const int*   lens  = (const int*)d_in[2];
    float* out = (float*)d_out;

    k_fused<<<dim3(TILES, BB), 256>>>(preds, targs, lens, out);
}